// round 1
// baseline (speedup 1.0000x reference)
#include <cuda_runtime.h>
#include <math.h>

#define NN_ 1536
#define DD_ 768
#define HH_ 64
#define PLANE (NN_ * NN_)

// Scratch (fully overwritten every launch -> graph-replay safe)
__device__ float g_part[6 * NN_ * 128]; // k-split partials of E@[W1a|W1b]
__device__ float g_A[NN_ * HH_];        // ha - g
__device__ float g_B[NN_ * HH_];        // hb + g + b1
__device__ float g_pv[NN_ * 6];         // pos(3), vel(3)

// ---------------------------------------------------------------------------
// Kernel 1: partial GEMM. grid (48, 6), 256 threads.
// Block (ib, ks): rows ib*32..+31, k-chunk ks*128..+127, all 128 output cols
// (cols 0..63 = W1a contribution, 64..127 = W1b contribution).
// ---------------------------------------------------------------------------
__global__ __launch_bounds__(256) void gemm_partial_kernel(
    const float* __restrict__ E, const float* __restrict__ W1)
{
    __shared__ __align__(16) float sE[32 * 17];   // 32 rows x 16 k, pad 17
    __shared__ __align__(16) float sW[16 * 128];  // 16 k x 128 h2

    const int t  = threadIdx.x;
    const int ib = blockIdx.x;
    const int ks = blockIdx.y;
    const int lane32 = t & 31;   // h-group (float4 col index)
    const int ig     = t >> 5;   // i-group (4 rows each)

    float4 acc0 = make_float4(0.f, 0.f, 0.f, 0.f);
    float4 acc1 = acc0, acc2 = acc0, acc3 = acc0;

    for (int kt = 0; kt < 8; ++kt) {
        const int kbase = ks * 128 + kt * 16;
        // load E tile: 512 floats
        for (int idx = t; idx < 512; idx += 256) {
            int r = idx >> 4, c = idx & 15;
            sE[r * 17 + c] = E[(ib * 32 + r) * DD_ + kbase + c];
        }
        // load W tile: 2048 floats  (h2<64 -> W1a row k, else W1b row 768+k)
        for (int idx = t; idx < 2048; idx += 256) {
            int kk = idx >> 7, h2 = idx & 127;
            float v = (h2 < 64) ? W1[(kbase + kk) * 64 + h2]
                                : W1[(DD_ + kbase + kk) * 64 + (h2 - 64)];
            sW[kk * 128 + h2] = v;
        }
        __syncthreads();
#pragma unroll
        for (int kk = 0; kk < 16; ++kk) {
            float4 w = reinterpret_cast<const float4*>(sW)[kk * 32 + lane32];
            float e0 = sE[(ig * 4 + 0) * 17 + kk];
            float e1 = sE[(ig * 4 + 1) * 17 + kk];
            float e2 = sE[(ig * 4 + 2) * 17 + kk];
            float e3 = sE[(ig * 4 + 3) * 17 + kk];
            acc0.x = fmaf(e0, w.x, acc0.x); acc0.y = fmaf(e0, w.y, acc0.y);
            acc0.z = fmaf(e0, w.z, acc0.z); acc0.w = fmaf(e0, w.w, acc0.w);
            acc1.x = fmaf(e1, w.x, acc1.x); acc1.y = fmaf(e1, w.y, acc1.y);
            acc1.z = fmaf(e1, w.z, acc1.z); acc1.w = fmaf(e1, w.w, acc1.w);
            acc2.x = fmaf(e2, w.x, acc2.x); acc2.y = fmaf(e2, w.y, acc2.y);
            acc2.z = fmaf(e2, w.z, acc2.z); acc2.w = fmaf(e2, w.w, acc2.w);
            acc3.x = fmaf(e3, w.x, acc3.x); acc3.y = fmaf(e3, w.y, acc3.y);
            acc3.z = fmaf(e3, w.z, acc3.z); acc3.w = fmaf(e3, w.w, acc3.w);
        }
        __syncthreads();
    }

    float4* dst = reinterpret_cast<float4*>(g_part) + (size_t)ks * (NN_ * 32);
    int ibase = ib * 32 + ig * 4;
    dst[(ibase + 0) * 32 + lane32] = acc0;
    dst[(ibase + 1) * 32 + lane32] = acc1;
    dst[(ibase + 2) * 32 + lane32] = acc2;
    dst[(ibase + 3) * 32 + lane32] = acc3;
}

// ---------------------------------------------------------------------------
// Kernel 2: reduce partials + fold geometry terms. grid 1536, 64 threads.
// ---------------------------------------------------------------------------
__global__ __launch_bounds__(64) void fold_kernel(
    const float* __restrict__ pos, const float* __restrict__ prev,
    const float* __restrict__ W1, const float* __restrict__ b1)
{
    const int i = blockIdx.x;
    const int h = threadIdx.x;

    float suma = 0.f, sumb = 0.f;
#pragma unroll
    for (int s = 0; s < 6; ++s) {
        suma += g_part[(size_t)s * (NN_ * 128) + i * 128 + h];
        sumb += g_part[(size_t)s * (NN_ * 128) + i * 128 + 64 + h];
    }
    float px = pos[i * 3 + 0], py = pos[i * 3 + 1], pz = pos[i * 3 + 2];
    float vx = px - prev[i * 3 + 0];
    float vy = py - prev[i * 3 + 1];
    float vz = pz - prev[i * 3 + 2];

    const float* Ws = W1 + 2 * DD_ * 64;  // W1s rows (8 x 64)
    float g = px * Ws[0 * 64 + h] + py * Ws[1 * 64 + h] + pz * Ws[2 * 64 + h]
            + vx * Ws[4 * 64 + h] + vy * Ws[5 * 64 + h] + vz * Ws[6 * 64 + h]
            + py * Ws[7 * 64 + h];

    g_A[i * 64 + h] = suma - g;
    g_B[i * 64 + h] = sumb + g + b1[h];

    if (h == 0) {
        g_pv[i * 6 + 0] = px; g_pv[i * 6 + 1] = py; g_pv[i * 6 + 2] = pz;
        g_pv[i * 6 + 3] = vx; g_pv[i * 6 + 4] = vy; g_pv[i * 6 + 5] = vz;
    }
}

// ---------------------------------------------------------------------------
// Kernel 3: pairwise. grid (48, 48), block (16, 16). Each thread: 2x2 strided
// micro-tile i in {ty, ty+16}, j in {tx, tx+16}.
// ---------------------------------------------------------------------------
__global__ __launch_bounds__(256) void pair_kernel(
    const float* __restrict__ W1, const float* __restrict__ W2,
    const float* __restrict__ b2, float* __restrict__ out)
{
    __shared__ __align__(16) float sA[32 * 68];  // rows padded to 68 floats
    __shared__ __align__(16) float sB[32 * 68];
    __shared__ __align__(16) float sW2[64 * 4];
    __shared__ __align__(16) float sW3[64];
    __shared__ float sPVi[32 * 6];
    __shared__ float sPVj[32 * 6];

    const int tx = threadIdx.x, ty = threadIdx.y;
    const int t  = ty * 16 + tx;
    const int i0 = blockIdx.y * 32;
    const int j0 = blockIdx.x * 32;

    // load A/B tiles (512 float4 each)
    for (int idx = t; idx < 512; idx += 256) {
        int r = idx >> 4, c = idx & 15;
        reinterpret_cast<float4*>(sA)[r * 17 + c] =
            reinterpret_cast<const float4*>(g_A)[(i0 + r) * 16 + c];
        reinterpret_cast<float4*>(sB)[r * 17 + c] =
            reinterpret_cast<const float4*>(g_B)[(j0 + r) * 16 + c];
    }
    if (t < 64) {
        reinterpret_cast<float4*>(sW2)[t] = reinterpret_cast<const float4*>(W2)[t];
        sW3[t] = W1[(2 * DD_ + 3) * 64 + t];  // w3 = W1s row 3 (distance)
    }
    for (int idx = t; idx < 192; idx += 256) {
        sPVi[idx] = g_pv[i0 * 6 + idx];
        sPVj[idx] = g_pv[j0 * 6 + idx];
    }
    __syncthreads();

    // geometry for the 4 pairs
    float dist[4], clos[4], vdif[4];
#pragma unroll
    for (int p = 0; p < 2; ++p) {
        int ri = ty + p * 16;
        float pix = sPVi[ri * 6 + 0], piy = sPVi[ri * 6 + 1], piz = sPVi[ri * 6 + 2];
        float vix = sPVi[ri * 6 + 3], viy = sPVi[ri * 6 + 4], viz = sPVi[ri * 6 + 5];
#pragma unroll
        for (int q = 0; q < 2; ++q) {
            int rj = tx + q * 16;
            float rpx = sPVj[rj * 6 + 0] - pix;
            float rpy = sPVj[rj * 6 + 1] - piy;
            float rpz = sPVj[rj * 6 + 2] - piz;
            float rvx = sPVj[rj * 6 + 3] - vix;
            float rvy = sPVj[rj * 6 + 4] - viy;
            float rvz = sPVj[rj * 6 + 5] - viz;
            float d2 = rpx * rpx + rpy * rpy + rpz * rpz;
            float d  = sqrtf(d2);
            float dot = rpx * rvx + rpy * rvy + rpz * rvz;
            int pq = p * 2 + q;
            dist[pq] = d;
            clos[pq] = -dot / fmaxf(d, 1e-6f);
            vdif[pq] = rpy;
        }
    }

    float4 acc[4];
#pragma unroll
    for (int pq = 0; pq < 4; ++pq) acc[pq] = make_float4(0.f, 0.f, 0.f, 0.f);

    const float4* A4  = reinterpret_cast<const float4*>(sA);
    const float4* B4  = reinterpret_cast<const float4*>(sB);
    const float4* W24 = reinterpret_cast<const float4*>(sW2);
    const float4* W34 = reinterpret_cast<const float4*>(sW3);

#pragma unroll
    for (int h4 = 0; h4 < 16; ++h4) {
        float4 a[2], b[2];
        a[0] = A4[ty * 17 + h4];
        a[1] = A4[(ty + 16) * 17 + h4];
        b[0] = B4[tx * 17 + h4];
        b[1] = B4[(tx + 16) * 17 + h4];
        float4 w3  = W34[h4];
        float4 w20 = W24[4 * h4 + 0];
        float4 w21 = W24[4 * h4 + 1];
        float4 w22 = W24[4 * h4 + 2];
        float4 w23 = W24[4 * h4 + 3];
#pragma unroll
        for (int p = 0; p < 2; ++p) {
#pragma unroll
            for (int q = 0; q < 2; ++q) {
                const int pq = p * 2 + q;
                const float dd = dist[pq];
                float h0 = fmaxf(fmaf(dd, w3.x, a[p].x + b[q].x), 0.f);
                float h1 = fmaxf(fmaf(dd, w3.y, a[p].y + b[q].y), 0.f);
                float h2 = fmaxf(fmaf(dd, w3.z, a[p].z + b[q].z), 0.f);
                float h3 = fmaxf(fmaf(dd, w3.w, a[p].w + b[q].w), 0.f);
                float4 ac = acc[pq];
                ac.x = fmaf(h0, w20.x, ac.x); ac.y = fmaf(h0, w20.y, ac.y);
                ac.z = fmaf(h0, w20.z, ac.z); ac.w = fmaf(h0, w20.w, ac.w);
                ac.x = fmaf(h1, w21.x, ac.x); ac.y = fmaf(h1, w21.y, ac.y);
                ac.z = fmaf(h1, w21.z, ac.z); ac.w = fmaf(h1, w21.w, ac.w);
                ac.x = fmaf(h2, w22.x, ac.x); ac.y = fmaf(h2, w22.y, ac.y);
                ac.z = fmaf(h2, w22.z, ac.z); ac.w = fmaf(h2, w22.w, ac.w);
                ac.x = fmaf(h3, w23.x, ac.x); ac.y = fmaf(h3, w23.y, ac.y);
                ac.z = fmaf(h3, w23.z, ac.z); ac.w = fmaf(h3, w23.w, ac.w);
                acc[pq] = ac;
            }
        }
    }

    const float b20 = __ldg(&b2[0]), b21 = __ldg(&b2[1]);
    const float b22 = __ldg(&b2[2]), b23 = __ldg(&b2[3]);

#pragma unroll
    for (int p = 0; p < 2; ++p) {
#pragma unroll
        for (int q = 0; q < 2; ++q) {
            const int pq = p * 2 + q;
            float l0 = acc[pq].x + b20;
            float l1 = acc[pq].y + b21;
            float l2 = acc[pq].z + b22;
            float l3 = acc[pq].w + b23;
            float m = fmaxf(fmaxf(l0, l1), fmaxf(l2, l3));
            float sum = expf(l0 - m) + expf(l1 - m) + expf(l2 - m) + expf(l3 - m);
            float conf = 1.0f / sum;
            int best = 0; float bm = l0;
            if (l1 > bm) { bm = l1; best = 1; }
            if (l2 > bm) { bm = l2; best = 2; }
            if (l3 > bm) { bm = l3; best = 3; }

            float d = dist[pq], c = clos[pq], v = vdif[pq];
            bool near  = d < 0.25f;
            bool appr  = !near && (c > 0.05f);
            bool flee  = !near && !appr && (c < -0.05f);
            bool above = !near && !appr && !flee && (fabsf(v) > 0.3f) && (d < 0.5f);

            int rt = near ? 0 : (appr ? 1 : (flee ? 2 : (above ? 3 : best)));
            float co = conf;
            if (near)              co = fmaxf(co, 0.8f);
            else if (appr || flee) co = fmaxf(co, 0.6f);
            else if (above)        co = fmaxf(co, 0.5f);

            int ig = i0 + ty + p * 16;
            int jg = j0 + tx + q * 16;
            size_t off = (size_t)ig * NN_ + jg;
            out[off]             = (float)rt;
            out[PLANE + off]     = co;
            out[2 * PLANE + off] = (jg > ig && co > 0.3f) ? 1.0f : 0.0f;
        }
    }
}

extern "C" void kernel_launch(void* const* d_in, const int* in_sizes, int n_in,
                              void* d_out, int out_size)
{
    const float* E    = (const float*)d_in[0];
    const float* pos  = (const float*)d_in[1];
    const float* prev = (const float*)d_in[2];
    const float* W1   = (const float*)d_in[3];
    const float* b1   = (const float*)d_in[4];
    const float* W2   = (const float*)d_in[5];
    const float* b2   = (const float*)d_in[6];
    float* out = (float*)d_out;

    gemm_partial_kernel<<<dim3(48, 6), 256>>>(E, W1);
    fold_kernel<<<NN_, 64>>>(pos, prev, W1, b1);
    pair_kernel<<<dim3(48, 48), dim3(16, 16)>>>(W1, W2, b2, out);
}